// round 15
// baseline (speedup 1.0000x reference)
#include <cuda_runtime.h>
#include <cuda_fp16.h>
#include <math.h>
#include <stdint.h>

#define BATCH  4
#define SEQ    2048
#define DMODEL 768
#define NHEAD  12
#define HDIM   64
#define MTOT   (BATCH*SEQ)

// ---------------- scratch (static device globals; no allocs allowed) ----------------
__device__ __half g_qh[MTOT*DMODEL];   // Q (x Wq^T + b) * 0.125, half, ctx-sorted rows
__device__ __half g_kh[MTOT*DMODEL];   // K, half, ctx-sorted rows
__device__ __half g_vh[MTOT*DMODEL];   // V^T, half: [b,h][dim][key(sorted)]
__device__ __half g_atth[MTOT*DMODEL]; // attention out, half, ORIGINAL rows (O GEMM input)
__device__ __half g_xh[MTOT*DMODEL];   // x, half
__device__ __half g_wqh[DMODEL*DMODEL];// weights, half
__device__ __half g_wkh[DMODEL*DMODEL];
__device__ __half g_wvh[DMODEL*DMODEL];
__device__ __half g_woh[DMODEL*DMODEL];
__device__ unsigned char g_ctx[MTOT];
__device__ int g_perm[MTOT];           // perm[new] = old  (per batch, ctx rows first)
__device__ int g_inv[MTOT];            // inv[old] = new
__device__ int g_nctx[BATCH];
__device__ int g_is_byte;

// ---------------- is_context dtype detection ----------------
__global__ void detect_dtype_kernel(const unsigned char* __restrict__ p, int nbytes) {
    __shared__ int found;
    if (threadIdx.x == 0) found = 0;
    __syncthreads();
    int loc = 0;
    for (int i = threadIdx.x; i < nbytes; i += blockDim.x)
        if ((i & 3) == 1 && p[i] != 0) loc = 1;
    if (loc) atomicOr(&found, 1);
    __syncthreads();
    if (threadIdx.x == 0) g_is_byte = found;
}

__global__ void ctx_convert_kernel(const void* __restrict__ p, int n) {
    int i = blockIdx.x * blockDim.x + threadIdx.x;
    if (i >= n) return;
    int v;
    if (g_is_byte) v = ((const unsigned char*)p)[i];
    else           v = ((const int*)p)[i];
    g_ctx[i] = v ? 1 : 0;
}

// ---------------- stable partition (ctx first) per batch: block scan ----------------
__global__ void build_perm_kernel() {
    __shared__ int partial[256];
    int b = blockIdx.x, t = threadIdx.x;
    int flags[8];
    int cnt = 0;
#pragma unroll
    for (int i = 0; i < 8; i++) {
        flags[i] = g_ctx[b * SEQ + t * 8 + i];
        cnt += flags[i];
    }
    partial[t] = cnt;
    __syncthreads();
    for (int off = 1; off < 256; off <<= 1) {
        int v = (t >= off) ? partial[t - off] : 0;
        __syncthreads();
        partial[t] += v;
        __syncthreads();
    }
    int total = partial[255];
    int run = partial[t] - cnt;
#pragma unroll
    for (int i = 0; i < 8; i++) {
        int old = t * 8 + i;
        int newpos;
        if (flags[i]) { newpos = run; run++; }
        else          { newpos = total + (old - run); }
        g_perm[b * SEQ + newpos] = old;
        g_inv[b * SEQ + old] = newpos;
    }
    if (t == 0) g_nctx[b] = total;
}

// ---------------- helpers ----------------
__device__ __forceinline__ void mma_f16(float* d, const uint32_t* a, const uint32_t* b, const float* c) {
    asm volatile(
        "mma.sync.aligned.m16n8k16.row.col.f32.f16.f16.f32 "
        "{%0,%1,%2,%3}, {%4,%5,%6,%7}, {%8,%9}, {%10,%11,%12,%13};"
        : "=f"(d[0]), "=f"(d[1]), "=f"(d[2]), "=f"(d[3])
        : "r"(a[0]), "r"(a[1]), "r"(a[2]), "r"(a[3]),
          "r"(b[0]), "r"(b[1]),
          "f"(c[0]), "f"(c[1]), "f"(c[2]), "f"(c[3]));
}

__device__ __forceinline__ uint32_t pack_h2(float lo, float hi) {
    __half2 h = __floats2half2_rn(lo, hi);
    return *(uint32_t*)&h;
}

__device__ __forceinline__ void cp_async16(uint32_t saddr, const void* gptr) {
    asm volatile("cp.async.cg.shared.global [%0], [%1], 16;" :: "r"(saddr), "l"(gptr));
}
__device__ __forceinline__ void cp_commit() {
    asm volatile("cp.async.commit_group;" ::: "memory");
}
__device__ __forceinline__ void cp_wait1() {
    asm volatile("cp.async.wait_group 1;" ::: "memory");
}
__device__ __forceinline__ void cp_wait0() {
    asm volatile("cp.async.wait_group 0;" ::: "memory");
}

// ---------------- fused half pre-conversion: x + all 4 weights in ONE launch ----------------
#define NX (MTOT*DMODEL)
#define NW (DMODEL*DMODEL)
__global__ void half_convert_all_kernel(const float* __restrict__ x,
                                        const float* __restrict__ Wq,
                                        const float* __restrict__ Wk,
                                        const float* __restrict__ Wv,
                                        const float* __restrict__ Wo) {
    int total = NX + 4 * NW;
    int stride = gridDim.x * blockDim.x;
    for (int i = blockIdx.x * blockDim.x + threadIdx.x; i < total; i += stride) {
        if (i < NX) {
            g_xh[i] = __float2half_rn(x[i]);
        } else {
            int j = i - NX;
            int wsel = j / NW;
            int off  = j - wsel * NW;
            const float* src = (wsel == 0) ? Wq : (wsel == 1) ? Wk : (wsel == 2) ? Wv : Wo;
            __half*      dst = (wsel == 0) ? g_wqh : (wsel == 1) ? g_wkh : (wsel == 2) ? g_wvh : g_woh;
            dst[off] = __float2half_rn(src[off]);
        }
    }
}

// ---------------- fp16 tensor-core GEMM, cp.async double-buffered, BK=64 (round-14, kept) ----------------
#define GROWH 72
#define GBUFH (128*GROWH)
__global__ __launch_bounds__(256, 2) void gemm_f16_kernel(
    const __half* __restrict__ A,
    const __half* __restrict__ W0, const float* __restrict__ b0, void* __restrict__ C0,
    const __half* __restrict__ W1, const float* __restrict__ b1, void* __restrict__ C1,
    const __half* __restrict__ W2, const float* __restrict__ b2, void* __restrict__ C2,
    int out_mode)
{
    extern __shared__ __half smh[];
    __half* As = smh;               // [2][128][GROWH]
    __half* Bs = smh + 2 * GBUFH;   // [2][128][GROWH]

    int z = blockIdx.z;
    const __half* W   = (z == 0) ? W0 : (z == 1) ? W1 : W2;
    const float* bias = (z == 0) ? b0 : (z == 1) ? b1 : b2;
    void*        C    = (z == 0) ? C0 : (z == 1) ? C1 : C2;

    int t    = threadIdx.x;
    int lane = t & 31;
    int warp = t >> 5;
    int g    = lane >> 2;
    int tq   = lane & 3;
    int wm   = (warp & 3) * 32;
    int wn   = (warp >> 2) * 64;
    int m0   = blockIdx.y * 128;
    int n0   = blockIdx.x * 128;

    float acc[2][8][4];
#pragma unroll
    for (int mt = 0; mt < 2; mt++)
#pragma unroll
        for (int nt = 0; nt < 8; nt++)
#pragma unroll
            for (int c = 0; c < 4; c++) acc[mt][nt][c] = 0.f;

    uint32_t as_s = (uint32_t)__cvta_generic_to_shared(As);
    uint32_t bs_s = (uint32_t)__cvta_generic_to_shared(Bs);

    auto stage = [&](int buf, int k0) {
        uint32_t bo = (uint32_t)buf * GBUFH * 2;
#pragma unroll
        for (int u = 0; u < 4; u++) {
            int c = t + 256 * u;
            int row = c >> 3, c16 = c & 7;
            uint32_t soff = bo + (uint32_t)(row * GROWH + c16 * 8) * 2;
            cp_async16(as_s + soff, A + (size_t)(m0 + row) * DMODEL + k0 + c16 * 8);
            cp_async16(bs_s + soff, W + (size_t)(n0 + row) * DMODEL + k0 + c16 * 8);
        }
        cp_commit();
    };

    stage(0, 0);

    const int NI = DMODEL / 64;   // 12
    for (int iter = 0; iter < NI; iter++) {
        int buf = iter & 1;
        if (iter + 1 < NI) {
            stage(buf ^ 1, (iter + 1) * 64);
            cp_wait1();
        } else {
            cp_wait0();
        }
        __syncthreads();

        const __half* A2 = As + buf * GBUFH;
        const __half* B2 = Bs + buf * GBUFH;

#pragma unroll
        for (int kst = 0; kst < 4; kst++) {
            int kb = kst * 16;
            uint32_t af[2][4];
#pragma unroll
            for (int mt = 0; mt < 2; mt++) {
                int rb = wm + mt * 16;
                af[mt][0] = *(const uint32_t*)&A2[(rb + g    ) * GROWH + kb + 2*tq    ];
                af[mt][1] = *(const uint32_t*)&A2[(rb + g + 8) * GROWH + kb + 2*tq    ];
                af[mt][2] = *(const uint32_t*)&A2[(rb + g    ) * GROWH + kb + 2*tq + 8];
                af[mt][3] = *(const uint32_t*)&A2[(rb + g + 8) * GROWH + kb + 2*tq + 8];
            }
#pragma unroll
            for (int nt = 0; nt < 8; nt++) {
                uint32_t bf[2];
                bf[0] = *(const uint32_t*)&B2[(wn + nt*8 + g) * GROWH + kb + 2*tq    ];
                bf[1] = *(const uint32_t*)&B2[(wn + nt*8 + g) * GROWH + kb + 2*tq + 8];
                mma_f16(acc[0][nt], af[0], bf, acc[0][nt]);
                mma_f16(acc[1][nt], af[1], bf, acc[1][nt]);
            }
        }
        __syncthreads();
    }

#pragma unroll
    for (int mt = 0; mt < 2; mt++) {
        int row = m0 + wm + mt * 16 + g;
        int r0 = row, r1 = row + 8;
        if (out_mode) {
            r0 = (row & ~(SEQ - 1)) + g_inv[row];
            r1 = ((row + 8) & ~(SEQ - 1)) + g_inv[row + 8];
        }
#pragma unroll
        for (int nt = 0; nt < 8; nt++) {
            int col = n0 + wn + nt * 8 + 2 * tq;
            float b0v = bias[col], b1v = bias[col + 1];
            float v00 = acc[mt][nt][0] + b0v, v01 = acc[mt][nt][1] + b1v;
            float v10 = acc[mt][nt][2] + b0v, v11 = acc[mt][nt][3] + b1v;
            if (!out_mode) {
                float* Cf = (float*)C;
                *(float2*)&Cf[(size_t)r0 * DMODEL + col] = make_float2(v00, v01);
                *(float2*)&Cf[(size_t)r1 * DMODEL + col] = make_float2(v10, v11);
            } else if (z <= 1) {
                float s = (z == 0) ? 0.125f : 1.0f;
                __half* Ch = (__half*)C;
                *(uint32_t*)&Ch[(size_t)r0 * DMODEL + col] = pack_h2(v00 * s, v01 * s);
                *(uint32_t*)&Ch[(size_t)r1 * DMODEL + col] = pack_h2(v10 * s, v11 * s);
            } else {
                __half* Vh = (__half*)C;
                int hh = col >> 6, d = col & 63;
                int b0i = r0 >> 11, k0i = r0 & (SEQ - 1);
                int b1i = r1 >> 11, k1i = r1 & (SEQ - 1);
                size_t base0 = (((size_t)b0i * NHEAD + hh) * HDIM + d) * SEQ;
                size_t base1 = (((size_t)b1i * NHEAD + hh) * HDIM + d) * SEQ;
                Vh[base0 + k0i]       = __float2half_rn(v00);
                Vh[base0 + SEQ + k0i] = __float2half_rn(v01);
                Vh[base1 + k1i]       = __float2half_rn(v10);
                Vh[base1 + SEQ + k1i] = __float2half_rn(v11);
            }
        }
    }
}

// ---------------- Flash attention: fp16, ctx-sorted, 3-stage cp.async ring ----------------
// ONE __syncthreads per tile: wait_group -> sync -> stage(tile+2) -> compute(tile).
// Buffer (tile+2)%3 was last read at iter tile-1; every warp has passed this
// iter's sync only after finishing that compute, so the overwrite is race-free.
// Skip-rescale: when the running max is unchanged for both row groups, corr==1
// exactly -> skip the 2 exps + 32 FMULs (scalar-only region, divergence-safe).
__global__ __launch_bounds__(256, 2) void attn_tc_kernel() {
    __shared__ __align__(16) uint32_t Ksw[3][32][36];
    __shared__ __align__(16) uint32_t Vtw[3][64][20];
    __shared__ __align__(16) uint32_t Ps[8][16][20];

    int t    = threadIdx.x;
    int lane = t & 31;
    int w    = t >> 5;
    int g    = lane >> 2;
    int tq   = lane & 3;

    int b  = blockIdx.z;
    int h  = blockIdx.y;
    int qrow = blockIdx.x * 128 + w * 16;     // sorted position
    int nctx = g_nctx[b];

    bool all_ctx = (blockIdx.x * 128 + 128) <= nctx;
    int NT_cta = all_ctx ? (nctx + 31) / 32 : (SEQ / 32);

    uint32_t qa[4][4];
    {
        const __half* qb = g_qh + (size_t)(b * SEQ + qrow) * DMODEL + h * HDIM;
#pragma unroll
        for (int kst = 0; kst < 4; kst++) {
            qa[kst][0] = *(const uint32_t*)&qb[(size_t)g       * DMODEL + kst*16 + 2*tq    ];
            qa[kst][1] = *(const uint32_t*)&qb[(size_t)(g + 8) * DMODEL + kst*16 + 2*tq    ];
            qa[kst][2] = *(const uint32_t*)&qb[(size_t)g       * DMODEL + kst*16 + 2*tq + 8];
            qa[kst][3] = *(const uint32_t*)&qb[(size_t)(g + 8) * DMODEL + kst*16 + 2*tq + 8];
        }
    }
    float rf0 = (qrow + g     < nctx) ? 1.f : 0.f;
    float rf1 = (qrow + g + 8 < nctx) ? 1.f : 0.f;

    float o[8][4];
#pragma unroll
    for (int nt = 0; nt < 8; nt++)
#pragma unroll
        for (int c = 0; c < 4; c++) o[nt][c] = 0.f;
    float m0r = -1e30f, m1r = -1e30f, l0 = 0.f, l1 = 0.f;

    int kkey = t >> 3, kc = t & 7;
    int vdim = t >> 2, vc = t & 3;
    const __half* kb_g = g_kh + (size_t)(b * SEQ) * DMODEL + h * HDIM;
    const __half* vb_g = g_vh + ((size_t)b * NHEAD + h) * HDIM * SEQ;

    uint32_t ks_s = (uint32_t)__cvta_generic_to_shared(&Ksw[0][0][0]);
    uint32_t vs_s = (uint32_t)__cvta_generic_to_shared(&Vtw[0][0][0]);
    const uint32_t KBUF = 32 * 36 * 4;
    const uint32_t VBUF = 64 * 20 * 4;

    auto stage = [&](int buf, int kt) {
        cp_async16(ks_s + buf * KBUF + (uint32_t)(kkey * 36 + kc * 4) * 4,
                   kb_g + (size_t)(kt + kkey) * DMODEL + kc * 8);
        cp_async16(vs_s + buf * VBUF + (uint32_t)(vdim * 20 + vc * 4) * 4,
                   vb_g + (size_t)vdim * SEQ + kt + vc * 8);
        cp_commit();
    };

    stage(0, 0);
    if (NT_cta > 1) stage(1, 32);

    for (int tile = 0; tile < NT_cta; tile++) {
        int buf = tile % 3;
        if (tile + 1 < NT_cta) cp_wait1();
        else                   cp_wait0();
        __syncthreads();
        if (tile + 2 < NT_cta) stage((tile + 2) % 3, (tile + 2) * 32);

        int k0b = tile * 32;

        // ---- S = Q K^T (16 x 32) ----
        float sacc[4][4];
#pragma unroll
        for (int nt = 0; nt < 4; nt++)
#pragma unroll
            for (int c = 0; c < 4; c++) sacc[nt][c] = 0.f;
#pragma unroll
        for (int kst = 0; kst < 4; kst++) {
#pragma unroll
            for (int nt = 0; nt < 4; nt++) {
                uint32_t bf[2];
                bf[0] = Ksw[buf][nt*8 + g][kst*8 + tq    ];
                bf[1] = Ksw[buf][nt*8 + g][kst*8 + tq + 4];
                mma_f16(sacc[nt], qa[kst], bf, sacc[nt]);
            }
        }

        // ---- mask (additive -1e30; only when tile straddles/exceeds ctx region) ----
        if (k0b + 32 > nctx) {
#pragma unroll
            for (int nt = 0; nt < 4; nt++) {
                int col = k0b + nt*8 + 2*tq;
                float k0m = (col     < nctx) ? 0.f : -1e30f;
                float k1m = (col + 1 < nctx) ? 0.f : -1e30f;
                sacc[nt][0] = fmaf(rf0, k0m, sacc[nt][0]);
                sacc[nt][1] = fmaf(rf0, k1m, sacc[nt][1]);
                sacc[nt][2] = fmaf(rf1, k0m, sacc[nt][2]);
                sacc[nt][3] = fmaf(rf1, k1m, sacc[nt][3]);
            }
        }

        // ---- online softmax ----
        float mx0 = -1e30f, mx1 = -1e30f;
#pragma unroll
        for (int nt = 0; nt < 4; nt++) {
            mx0 = fmaxf(mx0, fmaxf(sacc[nt][0], sacc[nt][1]));
            mx1 = fmaxf(mx1, fmaxf(sacc[nt][2], sacc[nt][3]));
        }
        mx0 = fmaxf(mx0, __shfl_xor_sync(0xffffffffu, mx0, 1));
        mx0 = fmaxf(mx0, __shfl_xor_sync(0xffffffffu, mx0, 2));
        mx1 = fmaxf(mx1, __shfl_xor_sync(0xffffffffu, mx1, 1));
        mx1 = fmaxf(mx1, __shfl_xor_sync(0xffffffffu, mx1, 2));

        // skip-rescale when the max is unchanged (corr would be exactly 1)
        if (mx0 > m0r || mx1 > m1r) {
            float mn0 = fmaxf(m0r, mx0), mn1 = fmaxf(m1r, mx1);
            float corr0 = __expf(m0r - mn0), corr1 = __expf(m1r - mn1);
            m0r = mn0; m1r = mn1;
            l0 *= corr0; l1 *= corr1;
#pragma unroll
            for (int nt = 0; nt < 8; nt++) {
                o[nt][0] *= corr0; o[nt][1] *= corr0;
                o[nt][2] *= corr1; o[nt][3] *= corr1;
            }
        }

        float rs0 = 0.f, rs1 = 0.f;
        __syncwarp();
#pragma unroll
        for (int nt = 0; nt < 4; nt++) {
            float p00 = __expf(sacc[nt][0] - m0r);
            float p01 = __expf(sacc[nt][1] - m0r);
            float p10 = __expf(sacc[nt][2] - m1r);
            float p11 = __expf(sacc[nt][3] - m1r);
            rs0 += p00 + p01; rs1 += p10 + p11;
            int pw = nt*4 + tq;
            Ps[w][g    ][pw] = pack_h2(p00, p01);
            Ps[w][g + 8][pw] = pack_h2(p10, p11);
        }
        rs0 += __shfl_xor_sync(0xffffffffu, rs0, 1);
        rs0 += __shfl_xor_sync(0xffffffffu, rs0, 2);
        rs1 += __shfl_xor_sync(0xffffffffu, rs1, 1);
        rs1 += __shfl_xor_sync(0xffffffffu, rs1, 2);
        l0 += rs0;
        l1 += rs1;
        __syncwarp();

        // ---- O += P V (16 x 64, k=32) ----
#pragma unroll
        for (int c2 = 0; c2 < 2; c2++) {
            uint32_t ap[4];
            ap[0] = Ps[w][g    ][c2*8 + tq    ];
            ap[1] = Ps[w][g + 8][c2*8 + tq    ];
            ap[2] = Ps[w][g    ][c2*8 + tq + 4];
            ap[3] = Ps[w][g + 8][c2*8 + tq + 4];
#pragma unroll
            for (int nt = 0; nt < 8; nt++) {
                uint32_t bf[2];
                bf[0] = Vtw[buf][nt*8 + g][c2*8 + tq    ];
                bf[1] = Vtw[buf][nt*8 + g][c2*8 + tq + 4];
                mma_f16(o[nt], ap, bf, o[nt]);
            }
        }
    }

    // ---- normalize + write back to ORIGINAL rows as HALF (O GEMM input) ----
    float inv0 = 1.f / l0, inv1 = 1.f / l1;
    int orow0 = g_perm[b * SEQ + qrow + g    ];
    int orow1 = g_perm[b * SEQ + qrow + g + 8];
    __half* ob0 = g_atth + ((size_t)b * SEQ + orow0) * DMODEL + h * HDIM;
    __half* ob1 = g_atth + ((size_t)b * SEQ + orow1) * DMODEL + h * HDIM;
#pragma unroll
    for (int nt = 0; nt < 8; nt++) {
        int col = nt*8 + 2*tq;
        *(uint32_t*)&ob0[col] = pack_h2(o[nt][0] * inv0, o[nt][1] * inv0);
        *(uint32_t*)&ob1[col] = pack_h2(o[nt][2] * inv1, o[nt][3] * inv1);
    }
}

// ---------------- launch ----------------
extern "C" void kernel_launch(void* const* d_in, const int* in_sizes, int n_in,
                              void* d_out, int out_size) {
    const float* x   = (const float*)d_in[0];
    const void*  ctx = d_in[1];
    const float* Wq  = (const float*)d_in[2];
    const float* bq  = (const float*)d_in[3];
    const float* Wk  = (const float*)d_in[4];
    const float* bk  = (const float*)d_in[5];
    const float* Wv  = (const float*)d_in[6];
    const float* bv  = (const float*)d_in[7];
    const float* Wo  = (const float*)d_in[8];
    const float* bo  = (const float*)d_in[9];
    float* out = (float*)d_out;

    __half *qh, *kh, *vh, *ath, *xh, *wqh, *wkh, *wvh, *woh;
    cudaGetSymbolAddress((void**)&qh,  g_qh);
    cudaGetSymbolAddress((void**)&kh,  g_kh);
    cudaGetSymbolAddress((void**)&vh,  g_vh);
    cudaGetSymbolAddress((void**)&ath, g_atth);
    cudaGetSymbolAddress((void**)&xh,  g_xh);
    cudaGetSymbolAddress((void**)&wqh, g_wqh);
    cudaGetSymbolAddress((void**)&wkh, g_wkh);
    cudaGetSymbolAddress((void**)&wvh, g_wvh);
    cudaGetSymbolAddress((void**)&woh, g_woh);

    static bool attr_set = false;
    if (!attr_set) {
        cudaFuncSetAttribute(gemm_f16_kernel, cudaFuncAttributeMaxDynamicSharedMemorySize,
                             4 * GBUFH * (int)sizeof(__half));
        attr_set = true;
    }

    detect_dtype_kernel<<<1, 1024>>>((const unsigned char*)ctx, MTOT);
    ctx_convert_kernel<<<(MTOT + 255) / 256, 256>>>(ctx, MTOT);
    build_perm_kernel<<<BATCH, 256>>>();

    half_convert_all_kernel<<<1184, 256>>>(x, Wq, Wk, Wv, Wo);

    int smem = 4 * GBUFH * (int)sizeof(__half);   // 73728 B

    dim3 gqkv(DMODEL / 128, MTOT / 128, 3);
    gemm_f16_kernel<<<gqkv, 256, smem>>>(xh, wqh, bq, qh, wkh, bk, kh, wvh, bv, vh, 1);

    attn_tc_kernel<<<dim3(SEQ / 128, NHEAD, BATCH), 256>>>();

    dim3 go(DMODEL / 128, MTOT / 128, 1);
    gemm_f16_kernel<<<go, 256, smem>>>(ath, woh, bo, out, woh, bo, out, woh, bo, out, 0);
}

// round 16
// speedup vs baseline: 1.0200x; 1.0200x over previous
#include <cuda_runtime.h>
#include <cuda_fp16.h>
#include <math.h>
#include <stdint.h>

#define BATCH  4
#define SEQ    2048
#define DMODEL 768
#define NHEAD  12
#define HDIM   64
#define MTOT   (BATCH*SEQ)

// ---------------- scratch (static device globals; no allocs allowed) ----------------
__device__ __half g_qh[MTOT*DMODEL];   // Q (x Wq^T + b) * 0.125, half, ctx-sorted rows
__device__ __half g_kh[MTOT*DMODEL];   // K, half, ctx-sorted rows
__device__ __half g_vh[MTOT*DMODEL];   // V^T, half: [b,h][dim][key(sorted)]
__device__ __half g_atth[MTOT*DMODEL]; // attention out, half, ORIGINAL rows (O GEMM input)
__device__ __half g_xh[MTOT*DMODEL];   // x, half
__device__ __half g_wqh[DMODEL*DMODEL];// weights, half
__device__ __half g_wkh[DMODEL*DMODEL];
__device__ __half g_wvh[DMODEL*DMODEL];
__device__ __half g_woh[DMODEL*DMODEL];
__device__ unsigned char g_ctx[MTOT];
__device__ int g_perm[MTOT];           // perm[new] = old  (per batch, ctx rows first)
__device__ int g_inv[MTOT];            // inv[old] = new
__device__ int g_nctx[BATCH];
__device__ int g_is_byte;

// ---------------- is_context dtype detection ----------------
__global__ void detect_dtype_kernel(const unsigned char* __restrict__ p, int nbytes) {
    __shared__ int found;
    if (threadIdx.x == 0) found = 0;
    __syncthreads();
    int loc = 0;
    for (int i = threadIdx.x; i < nbytes; i += blockDim.x)
        if ((i & 3) == 1 && p[i] != 0) loc = 1;
    if (loc) atomicOr(&found, 1);
    __syncthreads();
    if (threadIdx.x == 0) g_is_byte = found;
}

__global__ void ctx_convert_kernel(const void* __restrict__ p, int n) {
    int i = blockIdx.x * blockDim.x + threadIdx.x;
    if (i >= n) return;
    int v;
    if (g_is_byte) v = ((const unsigned char*)p)[i];
    else           v = ((const int*)p)[i];
    g_ctx[i] = v ? 1 : 0;
}

// ---------------- stable partition (ctx first) per batch: block scan ----------------
__global__ void build_perm_kernel() {
    __shared__ int partial[256];
    int b = blockIdx.x, t = threadIdx.x;
    int flags[8];
    int cnt = 0;
#pragma unroll
    for (int i = 0; i < 8; i++) {
        flags[i] = g_ctx[b * SEQ + t * 8 + i];
        cnt += flags[i];
    }
    partial[t] = cnt;
    __syncthreads();
    for (int off = 1; off < 256; off <<= 1) {
        int v = (t >= off) ? partial[t - off] : 0;
        __syncthreads();
        partial[t] += v;
        __syncthreads();
    }
    int total = partial[255];
    int run = partial[t] - cnt;
#pragma unroll
    for (int i = 0; i < 8; i++) {
        int old = t * 8 + i;
        int newpos;
        if (flags[i]) { newpos = run; run++; }
        else          { newpos = total + (old - run); }
        g_perm[b * SEQ + newpos] = old;
        g_inv[b * SEQ + old] = newpos;
    }
    if (t == 0) g_nctx[b] = total;
}

// ---------------- helpers ----------------
__device__ __forceinline__ void mma_f16(float* d, const uint32_t* a, const uint32_t* b, const float* c) {
    asm volatile(
        "mma.sync.aligned.m16n8k16.row.col.f32.f16.f16.f32 "
        "{%0,%1,%2,%3}, {%4,%5,%6,%7}, {%8,%9}, {%10,%11,%12,%13};"
        : "=f"(d[0]), "=f"(d[1]), "=f"(d[2]), "=f"(d[3])
        : "r"(a[0]), "r"(a[1]), "r"(a[2]), "r"(a[3]),
          "r"(b[0]), "r"(b[1]),
          "f"(c[0]), "f"(c[1]), "f"(c[2]), "f"(c[3]));
}

__device__ __forceinline__ uint32_t pack_h2(float lo, float hi) {
    __half2 h = __floats2half2_rn(lo, hi);
    return *(uint32_t*)&h;
}

__device__ __forceinline__ void cp_async16(uint32_t saddr, const void* gptr) {
    asm volatile("cp.async.cg.shared.global [%0], [%1], 16;" :: "r"(saddr), "l"(gptr));
}
__device__ __forceinline__ void cp_commit() {
    asm volatile("cp.async.commit_group;" ::: "memory");
}
__device__ __forceinline__ void cp_wait1() {
    asm volatile("cp.async.wait_group 1;" ::: "memory");
}
__device__ __forceinline__ void cp_wait0() {
    asm volatile("cp.async.wait_group 0;" ::: "memory");
}

// ---------------- fused half pre-conversion, VECTORIZED (float2 -> half2) ----------------
#define NX (MTOT*DMODEL)
#define NW (DMODEL*DMODEL)
__global__ void half_convert_all_kernel(const float* __restrict__ x,
                                        const float* __restrict__ Wq,
                                        const float* __restrict__ Wk,
                                        const float* __restrict__ Wv,
                                        const float* __restrict__ Wo) {
    const int NXp = NX / 2, NWp = NW / 2;
    int totalPairs = NXp + 4 * NWp;
    int stride = gridDim.x * blockDim.x;
    for (int i = blockIdx.x * blockDim.x + threadIdx.x; i < totalPairs; i += stride) {
        float2 v;
        uint32_t* dst;
        if (i < NXp) {
            v = ((const float2*)x)[i];
            dst = (uint32_t*)g_xh + i;
        } else {
            int j = i - NXp;
            int wsel = j / NWp;
            int off  = j - wsel * NWp;
            const float* src = (wsel == 0) ? Wq : (wsel == 1) ? Wk : (wsel == 2) ? Wv : Wo;
            __half*      d   = (wsel == 0) ? g_wqh : (wsel == 1) ? g_wkh : (wsel == 2) ? g_wvh : g_woh;
            v = ((const float2*)src)[off];
            dst = (uint32_t*)d + off;
        }
        *dst = pack_h2(v.x, v.y);
    }
}

// ---------------- fp16 tensor-core GEMM, cp.async double-buffered, BK=64 (round-14, kept) ----------------
#define GROWH 72
#define GBUFH (128*GROWH)
__global__ __launch_bounds__(256, 2) void gemm_f16_kernel(
    const __half* __restrict__ A,
    const __half* __restrict__ W0, const float* __restrict__ b0, void* __restrict__ C0,
    const __half* __restrict__ W1, const float* __restrict__ b1, void* __restrict__ C1,
    const __half* __restrict__ W2, const float* __restrict__ b2, void* __restrict__ C2,
    int out_mode)
{
    extern __shared__ __half smh[];
    __half* As = smh;               // [2][128][GROWH]
    __half* Bs = smh + 2 * GBUFH;   // [2][128][GROWH]

    int z = blockIdx.z;
    const __half* W   = (z == 0) ? W0 : (z == 1) ? W1 : W2;
    const float* bias = (z == 0) ? b0 : (z == 1) ? b1 : b2;
    void*        C    = (z == 0) ? C0 : (z == 1) ? C1 : C2;

    int t    = threadIdx.x;
    int lane = t & 31;
    int warp = t >> 5;
    int g    = lane >> 2;
    int tq   = lane & 3;
    int wm   = (warp & 3) * 32;
    int wn   = (warp >> 2) * 64;
    int m0   = blockIdx.y * 128;
    int n0   = blockIdx.x * 128;

    float acc[2][8][4];
#pragma unroll
    for (int mt = 0; mt < 2; mt++)
#pragma unroll
        for (int nt = 0; nt < 8; nt++)
#pragma unroll
            for (int c = 0; c < 4; c++) acc[mt][nt][c] = 0.f;

    uint32_t as_s = (uint32_t)__cvta_generic_to_shared(As);
    uint32_t bs_s = (uint32_t)__cvta_generic_to_shared(Bs);

    auto stage = [&](int buf, int k0) {
        uint32_t bo = (uint32_t)buf * GBUFH * 2;
#pragma unroll
        for (int u = 0; u < 4; u++) {
            int c = t + 256 * u;
            int row = c >> 3, c16 = c & 7;
            uint32_t soff = bo + (uint32_t)(row * GROWH + c16 * 8) * 2;
            cp_async16(as_s + soff, A + (size_t)(m0 + row) * DMODEL + k0 + c16 * 8);
            cp_async16(bs_s + soff, W + (size_t)(n0 + row) * DMODEL + k0 + c16 * 8);
        }
        cp_commit();
    };

    stage(0, 0);

    const int NI = DMODEL / 64;   // 12
    for (int iter = 0; iter < NI; iter++) {
        int buf = iter & 1;
        if (iter + 1 < NI) {
            stage(buf ^ 1, (iter + 1) * 64);
            cp_wait1();
        } else {
            cp_wait0();
        }
        __syncthreads();

        const __half* A2 = As + buf * GBUFH;
        const __half* B2 = Bs + buf * GBUFH;

#pragma unroll
        for (int kst = 0; kst < 4; kst++) {
            int kb = kst * 16;
            uint32_t af[2][4];
#pragma unroll
            for (int mt = 0; mt < 2; mt++) {
                int rb = wm + mt * 16;
                af[mt][0] = *(const uint32_t*)&A2[(rb + g    ) * GROWH + kb + 2*tq    ];
                af[mt][1] = *(const uint32_t*)&A2[(rb + g + 8) * GROWH + kb + 2*tq    ];
                af[mt][2] = *(const uint32_t*)&A2[(rb + g    ) * GROWH + kb + 2*tq + 8];
                af[mt][3] = *(const uint32_t*)&A2[(rb + g + 8) * GROWH + kb + 2*tq + 8];
            }
#pragma unroll
            for (int nt = 0; nt < 8; nt++) {
                uint32_t bf[2];
                bf[0] = *(const uint32_t*)&B2[(wn + nt*8 + g) * GROWH + kb + 2*tq    ];
                bf[1] = *(const uint32_t*)&B2[(wn + nt*8 + g) * GROWH + kb + 2*tq + 8];
                mma_f16(acc[0][nt], af[0], bf, acc[0][nt]);
                mma_f16(acc[1][nt], af[1], bf, acc[1][nt]);
            }
        }
        __syncthreads();
    }

#pragma unroll
    for (int mt = 0; mt < 2; mt++) {
        int row = m0 + wm + mt * 16 + g;
        int r0 = row, r1 = row + 8;
        if (out_mode) {
            r0 = (row & ~(SEQ - 1)) + g_inv[row];
            r1 = ((row + 8) & ~(SEQ - 1)) + g_inv[row + 8];
        }
#pragma unroll
        for (int nt = 0; nt < 8; nt++) {
            int col = n0 + wn + nt * 8 + 2 * tq;
            float b0v = bias[col], b1v = bias[col + 1];
            float v00 = acc[mt][nt][0] + b0v, v01 = acc[mt][nt][1] + b1v;
            float v10 = acc[mt][nt][2] + b0v, v11 = acc[mt][nt][3] + b1v;
            if (!out_mode) {
                float* Cf = (float*)C;
                *(float2*)&Cf[(size_t)r0 * DMODEL + col] = make_float2(v00, v01);
                *(float2*)&Cf[(size_t)r1 * DMODEL + col] = make_float2(v10, v11);
            } else if (z <= 1) {
                float s = (z == 0) ? 0.125f : 1.0f;
                __half* Ch = (__half*)C;
                *(uint32_t*)&Ch[(size_t)r0 * DMODEL + col] = pack_h2(v00 * s, v01 * s);
                *(uint32_t*)&Ch[(size_t)r1 * DMODEL + col] = pack_h2(v10 * s, v11 * s);
            } else {
                __half* Vh = (__half*)C;
                int hh = col >> 6, d = col & 63;
                int b0i = r0 >> 11, k0i = r0 & (SEQ - 1);
                int b1i = r1 >> 11, k1i = r1 & (SEQ - 1);
                size_t base0 = (((size_t)b0i * NHEAD + hh) * HDIM + d) * SEQ;
                size_t base1 = (((size_t)b1i * NHEAD + hh) * HDIM + d) * SEQ;
                Vh[base0 + k0i]       = __float2half_rn(v00);
                Vh[base0 + SEQ + k0i] = __float2half_rn(v01);
                Vh[base1 + k1i]       = __float2half_rn(v10);
                Vh[base1 + SEQ + k1i] = __float2half_rn(v11);
            }
        }
    }
}

// ---------------- Flash attention: fp16, ctx-sorted, 3-stage ring, round-14 softmax ----------------
// ONE __syncthreads per tile: wait_group -> sync -> stage(tile+2) -> compute(tile).
// Buffer (tile+2)%3 was last read at iter tile-1; every warp has passed this
// iter's sync only after finishing that compute, so the overwrite is race-free.
// Softmax rescale is UNCONDITIONAL (round-15's skip branch regressed: per-lane
// divergence made it skip nothing while paying the branch envelope).
__global__ __launch_bounds__(256, 2) void attn_tc_kernel() {
    __shared__ __align__(16) uint32_t Ksw[3][32][36];
    __shared__ __align__(16) uint32_t Vtw[3][64][20];
    __shared__ __align__(16) uint32_t Ps[8][16][20];

    int t    = threadIdx.x;
    int lane = t & 31;
    int w    = t >> 5;
    int g    = lane >> 2;
    int tq   = lane & 3;

    int b  = blockIdx.z;
    int h  = blockIdx.y;
    int qrow = blockIdx.x * 128 + w * 16;     // sorted position
    int nctx = g_nctx[b];

    bool all_ctx = (blockIdx.x * 128 + 128) <= nctx;
    int NT_cta = all_ctx ? (nctx + 31) / 32 : (SEQ / 32);

    uint32_t qa[4][4];
    {
        const __half* qb = g_qh + (size_t)(b * SEQ + qrow) * DMODEL + h * HDIM;
#pragma unroll
        for (int kst = 0; kst < 4; kst++) {
            qa[kst][0] = *(const uint32_t*)&qb[(size_t)g       * DMODEL + kst*16 + 2*tq    ];
            qa[kst][1] = *(const uint32_t*)&qb[(size_t)(g + 8) * DMODEL + kst*16 + 2*tq    ];
            qa[kst][2] = *(const uint32_t*)&qb[(size_t)g       * DMODEL + kst*16 + 2*tq + 8];
            qa[kst][3] = *(const uint32_t*)&qb[(size_t)(g + 8) * DMODEL + kst*16 + 2*tq + 8];
        }
    }
    float rf0 = (qrow + g     < nctx) ? 1.f : 0.f;
    float rf1 = (qrow + g + 8 < nctx) ? 1.f : 0.f;

    float o[8][4];
#pragma unroll
    for (int nt = 0; nt < 8; nt++)
#pragma unroll
        for (int c = 0; c < 4; c++) o[nt][c] = 0.f;
    float m0r = -1e30f, m1r = -1e30f, l0 = 0.f, l1 = 0.f;

    int kkey = t >> 3, kc = t & 7;
    int vdim = t >> 2, vc = t & 3;
    const __half* kb_g = g_kh + (size_t)(b * SEQ) * DMODEL + h * HDIM;
    const __half* vb_g = g_vh + ((size_t)b * NHEAD + h) * HDIM * SEQ;

    uint32_t ks_s = (uint32_t)__cvta_generic_to_shared(&Ksw[0][0][0]);
    uint32_t vs_s = (uint32_t)__cvta_generic_to_shared(&Vtw[0][0][0]);
    const uint32_t KBUF = 32 * 36 * 4;
    const uint32_t VBUF = 64 * 20 * 4;

    auto stage = [&](int buf, int kt) {
        cp_async16(ks_s + buf * KBUF + (uint32_t)(kkey * 36 + kc * 4) * 4,
                   kb_g + (size_t)(kt + kkey) * DMODEL + kc * 8);
        cp_async16(vs_s + buf * VBUF + (uint32_t)(vdim * 20 + vc * 4) * 4,
                   vb_g + (size_t)vdim * SEQ + kt + vc * 8);
        cp_commit();
    };

    stage(0, 0);
    if (NT_cta > 1) stage(1, 32);

    for (int tile = 0; tile < NT_cta; tile++) {
        int buf = tile % 3;
        if (tile + 1 < NT_cta) cp_wait1();
        else                   cp_wait0();
        __syncthreads();
        if (tile + 2 < NT_cta) stage((tile + 2) % 3, (tile + 2) * 32);

        int k0b = tile * 32;

        // ---- S = Q K^T (16 x 32) ----
        float sacc[4][4];
#pragma unroll
        for (int nt = 0; nt < 4; nt++)
#pragma unroll
            for (int c = 0; c < 4; c++) sacc[nt][c] = 0.f;
#pragma unroll
        for (int kst = 0; kst < 4; kst++) {
#pragma unroll
            for (int nt = 0; nt < 4; nt++) {
                uint32_t bf[2];
                bf[0] = Ksw[buf][nt*8 + g][kst*8 + tq    ];
                bf[1] = Ksw[buf][nt*8 + g][kst*8 + tq + 4];
                mma_f16(sacc[nt], qa[kst], bf, sacc[nt]);
            }
        }

        // ---- mask (additive -1e30; only when tile straddles/exceeds ctx region) ----
        if (k0b + 32 > nctx) {
#pragma unroll
            for (int nt = 0; nt < 4; nt++) {
                int col = k0b + nt*8 + 2*tq;
                float k0m = (col     < nctx) ? 0.f : -1e30f;
                float k1m = (col + 1 < nctx) ? 0.f : -1e30f;
                sacc[nt][0] = fmaf(rf0, k0m, sacc[nt][0]);
                sacc[nt][1] = fmaf(rf0, k1m, sacc[nt][1]);
                sacc[nt][2] = fmaf(rf1, k0m, sacc[nt][2]);
                sacc[nt][3] = fmaf(rf1, k1m, sacc[nt][3]);
            }
        }

        // ---- online softmax (unconditional rescale, round-14 numerics) ----
        float mx0 = -1e30f, mx1 = -1e30f;
#pragma unroll
        for (int nt = 0; nt < 4; nt++) {
            mx0 = fmaxf(mx0, fmaxf(sacc[nt][0], sacc[nt][1]));
            mx1 = fmaxf(mx1, fmaxf(sacc[nt][2], sacc[nt][3]));
        }
        mx0 = fmaxf(mx0, __shfl_xor_sync(0xffffffffu, mx0, 1));
        mx0 = fmaxf(mx0, __shfl_xor_sync(0xffffffffu, mx0, 2));
        mx1 = fmaxf(mx1, __shfl_xor_sync(0xffffffffu, mx1, 1));
        mx1 = fmaxf(mx1, __shfl_xor_sync(0xffffffffu, mx1, 2));

        float mn0 = fmaxf(m0r, mx0), mn1 = fmaxf(m1r, mx1);
        float corr0 = __expf(m0r - mn0), corr1 = __expf(m1r - mn1);
        m0r = mn0; m1r = mn1;

        float rs0 = 0.f, rs1 = 0.f;
        __syncwarp();
#pragma unroll
        for (int nt = 0; nt < 4; nt++) {
            float p00 = __expf(sacc[nt][0] - mn0);
            float p01 = __expf(sacc[nt][1] - mn0);
            float p10 = __expf(sacc[nt][2] - mn1);
            float p11 = __expf(sacc[nt][3] - mn1);
            rs0 += p00 + p01; rs1 += p10 + p11;
            int pw = nt*4 + tq;
            Ps[w][g    ][pw] = pack_h2(p00, p01);
            Ps[w][g + 8][pw] = pack_h2(p10, p11);
        }
        rs0 += __shfl_xor_sync(0xffffffffu, rs0, 1);
        rs0 += __shfl_xor_sync(0xffffffffu, rs0, 2);
        rs1 += __shfl_xor_sync(0xffffffffu, rs1, 1);
        rs1 += __shfl_xor_sync(0xffffffffu, rs1, 2);
        l0 = l0 * corr0 + rs0;
        l1 = l1 * corr1 + rs1;

#pragma unroll
        for (int nt = 0; nt < 8; nt++) {
            o[nt][0] *= corr0; o[nt][1] *= corr0;
            o[nt][2] *= corr1; o[nt][3] *= corr1;
        }
        __syncwarp();

        // ---- O += P V (16 x 64, k=32) ----
#pragma unroll
        for (int c2 = 0; c2 < 2; c2++) {
            uint32_t ap[4];
            ap[0] = Ps[w][g    ][c2*8 + tq    ];
            ap[1] = Ps[w][g + 8][c2*8 + tq    ];
            ap[2] = Ps[w][g    ][c2*8 + tq + 4];
            ap[3] = Ps[w][g + 8][c2*8 + tq + 4];
#pragma unroll
            for (int nt = 0; nt < 8; nt++) {
                uint32_t bf[2];
                bf[0] = Vtw[buf][nt*8 + g][c2*8 + tq    ];
                bf[1] = Vtw[buf][nt*8 + g][c2*8 + tq + 4];
                mma_f16(o[nt], ap, bf, o[nt]);
            }
        }
    }

    // ---- normalize + write back to ORIGINAL rows as HALF (O GEMM input) ----
    float inv0 = 1.f / l0, inv1 = 1.f / l1;
    int orow0 = g_perm[b * SEQ + qrow + g    ];
    int orow1 = g_perm[b * SEQ + qrow + g + 8];
    __half* ob0 = g_atth + ((size_t)b * SEQ + orow0) * DMODEL + h * HDIM;
    __half* ob1 = g_atth + ((size_t)b * SEQ + orow1) * DMODEL + h * HDIM;
#pragma unroll
    for (int nt = 0; nt < 8; nt++) {
        int col = nt*8 + 2*tq;
        *(uint32_t*)&ob0[col] = pack_h2(o[nt][0] * inv0, o[nt][1] * inv0);
        *(uint32_t*)&ob1[col] = pack_h2(o[nt][2] * inv1, o[nt][3] * inv1);
    }
}

// ---------------- launch ----------------
extern "C" void kernel_launch(void* const* d_in, const int* in_sizes, int n_in,
                              void* d_out, int out_size) {
    const float* x   = (const float*)d_in[0];
    const void*  ctx = d_in[1];
    const float* Wq  = (const float*)d_in[2];
    const float* bq  = (const float*)d_in[3];
    const float* Wk  = (const float*)d_in[4];
    const float* bk  = (const float*)d_in[5];
    const float* Wv  = (const float*)d_in[6];
    const float* bv  = (const float*)d_in[7];
    const float* Wo  = (const float*)d_in[8];
    const float* bo  = (const float*)d_in[9];
    float* out = (float*)d_out;

    __half *qh, *kh, *vh, *ath, *xh, *wqh, *wkh, *wvh, *woh;
    cudaGetSymbolAddress((void**)&qh,  g_qh);
    cudaGetSymbolAddress((void**)&kh,  g_kh);
    cudaGetSymbolAddress((void**)&vh,  g_vh);
    cudaGetSymbolAddress((void**)&ath, g_atth);
    cudaGetSymbolAddress((void**)&xh,  g_xh);
    cudaGetSymbolAddress((void**)&wqh, g_wqh);
    cudaGetSymbolAddress((void**)&wkh, g_wkh);
    cudaGetSymbolAddress((void**)&wvh, g_wvh);
    cudaGetSymbolAddress((void**)&woh, g_woh);

    static bool attr_set = false;
    if (!attr_set) {
        cudaFuncSetAttribute(gemm_f16_kernel, cudaFuncAttributeMaxDynamicSharedMemorySize,
                             4 * GBUFH * (int)sizeof(__half));
        attr_set = true;
    }

    detect_dtype_kernel<<<1, 1024>>>((const unsigned char*)ctx, MTOT);
    ctx_convert_kernel<<<(MTOT + 255) / 256, 256>>>(ctx, MTOT);
    build_perm_kernel<<<BATCH, 256>>>();

    half_convert_all_kernel<<<592, 256>>>(x, Wq, Wk, Wv, Wo);

    int smem = 4 * GBUFH * (int)sizeof(__half);   // 73728 B

    dim3 gqkv(DMODEL / 128, MTOT / 128, 3);
    gemm_f16_kernel<<<gqkv, 256, smem>>>(xh, wqh, bq, qh, wkh, bk, kh, wvh, bv, vh, 1);

    attn_tc_kernel<<<dim3(SEQ / 128, NHEAD, BATCH), 256>>>();

    dim3 go(DMODEL / 128, MTOT / 128, 1);
    gemm_f16_kernel<<<go, 256, smem>>>(ath, woh, bo, out, woh, bo, out, woh, bo, out, 0);
}

// round 17
// speedup vs baseline: 1.0992x; 1.0776x over previous
#include <cuda_runtime.h>
#include <cuda_fp16.h>
#include <math.h>
#include <stdint.h>

#define BATCH  4
#define SEQ    2048
#define DMODEL 768
#define NHEAD  12
#define HDIM   64
#define MTOT   (BATCH*SEQ)

// ---------------- scratch (static device globals; no allocs allowed) ----------------
__device__ __half g_qh[MTOT*DMODEL];   // Q (x Wq^T + b) * 0.125, half, ctx-sorted rows
__device__ __half g_kh[MTOT*DMODEL];   // K, half, ctx-sorted rows
__device__ __half g_vh[MTOT*DMODEL];   // V^T, half: [b,h][dim][key(sorted)]
__device__ __half g_atth[MTOT*DMODEL]; // attention out, half, ORIGINAL rows (O GEMM input)
__device__ __half g_xh[MTOT*DMODEL];   // x, half
__device__ __half g_wqh[DMODEL*DMODEL];// weights, half
__device__ __half g_wkh[DMODEL*DMODEL];
__device__ __half g_wvh[DMODEL*DMODEL];
__device__ __half g_woh[DMODEL*DMODEL];
__device__ int g_perm[MTOT];           // perm[new] = old  (per batch, ctx rows first)
__device__ int g_inv[MTOT];            // inv[old] = new
__device__ int g_nctx[BATCH];
__device__ int g_is_byte;

// ---------------- is_context dtype detection ----------------
__global__ void detect_dtype_kernel(const unsigned char* __restrict__ p, int nbytes) {
    __shared__ int found;
    if (threadIdx.x == 0) found = 0;
    __syncthreads();
    int loc = 0;
    for (int i = threadIdx.x; i < nbytes; i += blockDim.x)
        if ((i & 3) == 1 && p[i] != 0) loc = 1;
    if (loc) atomicOr(&found, 1);
    __syncthreads();
    if (threadIdx.x == 0) g_is_byte = found;
}

// ---------------- stable partition (ctx first) per batch, reading RAW ctx input ----------------
__global__ void build_perm_kernel(const void* __restrict__ p) {
    __shared__ int partial[256];
    int b = blockIdx.x, t = threadIdx.x;
    int is_byte = g_is_byte;
    int flags[8];
    int cnt = 0;
#pragma unroll
    for (int i = 0; i < 8; i++) {
        int old = b * SEQ + t * 8 + i;
        int v = is_byte ? (int)((const unsigned char*)p)[old] : ((const int*)p)[old];
        flags[i] = (v != 0);
        cnt += flags[i];
    }
    partial[t] = cnt;
    __syncthreads();
    for (int off = 1; off < 256; off <<= 1) {
        int v = (t >= off) ? partial[t - off] : 0;
        __syncthreads();
        partial[t] += v;
        __syncthreads();
    }
    int total = partial[255];
    int run = partial[t] - cnt;
#pragma unroll
    for (int i = 0; i < 8; i++) {
        int old = t * 8 + i;
        int newpos;
        if (flags[i]) { newpos = run; run++; }
        else          { newpos = total + (old - run); }
        g_perm[b * SEQ + newpos] = old;
        g_inv[b * SEQ + old] = newpos;
    }
    if (t == 0) g_nctx[b] = total;
}

// ---------------- helpers ----------------
__device__ __forceinline__ void mma_f16(float* d, const uint32_t* a, const uint32_t* b, const float* c) {
    asm volatile(
        "mma.sync.aligned.m16n8k16.row.col.f32.f16.f16.f32 "
        "{%0,%1,%2,%3}, {%4,%5,%6,%7}, {%8,%9}, {%10,%11,%12,%13};"
        : "=f"(d[0]), "=f"(d[1]), "=f"(d[2]), "=f"(d[3])
        : "r"(a[0]), "r"(a[1]), "r"(a[2]), "r"(a[3]),
          "r"(b[0]), "r"(b[1]),
          "f"(c[0]), "f"(c[1]), "f"(c[2]), "f"(c[3]));
}

__device__ __forceinline__ uint32_t pack_h2(float lo, float hi) {
    __half2 h = __floats2half2_rn(lo, hi);
    return *(uint32_t*)&h;
}

__device__ __forceinline__ void cp_async16(uint32_t saddr, const void* gptr) {
    asm volatile("cp.async.cg.shared.global [%0], [%1], 16;" :: "r"(saddr), "l"(gptr));
}
__device__ __forceinline__ void cp_commit() {
    asm volatile("cp.async.commit_group;" ::: "memory");
}
__device__ __forceinline__ void cp_wait1() {
    asm volatile("cp.async.wait_group 1;" ::: "memory");
}
__device__ __forceinline__ void cp_wait0() {
    asm volatile("cp.async.wait_group 0;" ::: "memory");
}

// ---------------- fused half pre-conversion, float4 vectorized ----------------
#define NX (MTOT*DMODEL)
#define NW (DMODEL*DMODEL)
__global__ void half_convert_all_kernel(const float* __restrict__ x,
                                        const float* __restrict__ Wq,
                                        const float* __restrict__ Wk,
                                        const float* __restrict__ Wv,
                                        const float* __restrict__ Wo) {
    const int NXq = NX / 4, NWq = NW / 4;
    int totalQuads = NXq + 4 * NWq;
    int stride = gridDim.x * blockDim.x;
    for (int i = blockIdx.x * blockDim.x + threadIdx.x; i < totalQuads; i += stride) {
        float4 v;
        uint2* dst;
        if (i < NXq) {
            v = ((const float4*)x)[i];
            dst = (uint2*)g_xh + i;
        } else {
            int j = i - NXq;
            int wsel = j / NWq;
            int off  = j - wsel * NWq;
            const float* src = (wsel == 0) ? Wq : (wsel == 1) ? Wk : (wsel == 2) ? Wv : Wo;
            __half*      d   = (wsel == 0) ? g_wqh : (wsel == 1) ? g_wkh : (wsel == 2) ? g_wvh : g_woh;
            v = ((const float4*)src)[off];
            dst = (uint2*)d + off;
        }
        uint2 o;
        o.x = pack_h2(v.x, v.y);
        o.y = pack_h2(v.z, v.w);
        *dst = o;
    }
}

// ---------------- fp16 tensor-core GEMM, cp.async double-buffered, BK=64 (round-14, kept) ----------------
#define GROWH 72
#define GBUFH (128*GROWH)
__global__ __launch_bounds__(256, 2) void gemm_f16_kernel(
    const __half* __restrict__ A,
    const __half* __restrict__ W0, const float* __restrict__ b0, void* __restrict__ C0,
    const __half* __restrict__ W1, const float* __restrict__ b1, void* __restrict__ C1,
    const __half* __restrict__ W2, const float* __restrict__ b2, void* __restrict__ C2,
    int out_mode)
{
    extern __shared__ __half smh[];
    __half* As = smh;               // [2][128][GROWH]
    __half* Bs = smh + 2 * GBUFH;   // [2][128][GROWH]

    int z = blockIdx.z;
    const __half* W   = (z == 0) ? W0 : (z == 1) ? W1 : W2;
    const float* bias = (z == 0) ? b0 : (z == 1) ? b1 : b2;
    void*        C    = (z == 0) ? C0 : (z == 1) ? C1 : C2;

    int t    = threadIdx.x;
    int lane = t & 31;
    int warp = t >> 5;
    int g    = lane >> 2;
    int tq   = lane & 3;
    int wm   = (warp & 3) * 32;
    int wn   = (warp >> 2) * 64;
    int m0   = blockIdx.y * 128;
    int n0   = blockIdx.x * 128;

    float acc[2][8][4];
#pragma unroll
    for (int mt = 0; mt < 2; mt++)
#pragma unroll
        for (int nt = 0; nt < 8; nt++)
#pragma unroll
            for (int c = 0; c < 4; c++) acc[mt][nt][c] = 0.f;

    uint32_t as_s = (uint32_t)__cvta_generic_to_shared(As);
    uint32_t bs_s = (uint32_t)__cvta_generic_to_shared(Bs);

    auto stage = [&](int buf, int k0) {
        uint32_t bo = (uint32_t)buf * GBUFH * 2;
#pragma unroll
        for (int u = 0; u < 4; u++) {
            int c = t + 256 * u;
            int row = c >> 3, c16 = c & 7;
            uint32_t soff = bo + (uint32_t)(row * GROWH + c16 * 8) * 2;
            cp_async16(as_s + soff, A + (size_t)(m0 + row) * DMODEL + k0 + c16 * 8);
            cp_async16(bs_s + soff, W + (size_t)(n0 + row) * DMODEL + k0 + c16 * 8);
        }
        cp_commit();
    };

    stage(0, 0);

    const int NI = DMODEL / 64;   // 12
    for (int iter = 0; iter < NI; iter++) {
        int buf = iter & 1;
        if (iter + 1 < NI) {
            stage(buf ^ 1, (iter + 1) * 64);
            cp_wait1();
        } else {
            cp_wait0();
        }
        __syncthreads();

        const __half* A2 = As + buf * GBUFH;
        const __half* B2 = Bs + buf * GBUFH;

#pragma unroll
        for (int kst = 0; kst < 4; kst++) {
            int kb = kst * 16;
            uint32_t af[2][4];
#pragma unroll
            for (int mt = 0; mt < 2; mt++) {
                int rb = wm + mt * 16;
                af[mt][0] = *(const uint32_t*)&A2[(rb + g    ) * GROWH + kb + 2*tq    ];
                af[mt][1] = *(const uint32_t*)&A2[(rb + g + 8) * GROWH + kb + 2*tq    ];
                af[mt][2] = *(const uint32_t*)&A2[(rb + g    ) * GROWH + kb + 2*tq + 8];
                af[mt][3] = *(const uint32_t*)&A2[(rb + g + 8) * GROWH + kb + 2*tq + 8];
            }
#pragma unroll
            for (int nt = 0; nt < 8; nt++) {
                uint32_t bf[2];
                bf[0] = *(const uint32_t*)&B2[(wn + nt*8 + g) * GROWH + kb + 2*tq    ];
                bf[1] = *(const uint32_t*)&B2[(wn + nt*8 + g) * GROWH + kb + 2*tq + 8];
                mma_f16(acc[0][nt], af[0], bf, acc[0][nt]);
                mma_f16(acc[1][nt], af[1], bf, acc[1][nt]);
            }
        }
        __syncthreads();
    }

#pragma unroll
    for (int mt = 0; mt < 2; mt++) {
        int row = m0 + wm + mt * 16 + g;
        int r0 = row, r1 = row + 8;
        if (out_mode) {
            r0 = (row & ~(SEQ - 1)) + g_inv[row];
            r1 = ((row + 8) & ~(SEQ - 1)) + g_inv[row + 8];
        }
#pragma unroll
        for (int nt = 0; nt < 8; nt++) {
            int col = n0 + wn + nt * 8 + 2 * tq;
            float b0v = bias[col], b1v = bias[col + 1];
            float v00 = acc[mt][nt][0] + b0v, v01 = acc[mt][nt][1] + b1v;
            float v10 = acc[mt][nt][2] + b0v, v11 = acc[mt][nt][3] + b1v;
            if (!out_mode) {
                float* Cf = (float*)C;
                *(float2*)&Cf[(size_t)r0 * DMODEL + col] = make_float2(v00, v01);
                *(float2*)&Cf[(size_t)r1 * DMODEL + col] = make_float2(v10, v11);
            } else if (z <= 1) {
                float s = (z == 0) ? 0.125f : 1.0f;
                __half* Ch = (__half*)C;
                *(uint32_t*)&Ch[(size_t)r0 * DMODEL + col] = pack_h2(v00 * s, v01 * s);
                *(uint32_t*)&Ch[(size_t)r1 * DMODEL + col] = pack_h2(v10 * s, v11 * s);
            } else {
                __half* Vh = (__half*)C;
                int hh = col >> 6, d = col & 63;
                int b0i = r0 >> 11, k0i = r0 & (SEQ - 1);
                int b1i = r1 >> 11, k1i = r1 & (SEQ - 1);
                size_t base0 = (((size_t)b0i * NHEAD + hh) * HDIM + d) * SEQ;
                size_t base1 = (((size_t)b1i * NHEAD + hh) * HDIM + d) * SEQ;
                Vh[base0 + k0i]       = __float2half_rn(v00);
                Vh[base0 + SEQ + k0i] = __float2half_rn(v01);
                Vh[base1 + k1i]       = __float2half_rn(v10);
                Vh[base1 + SEQ + k1i] = __float2half_rn(v11);
            }
        }
    }
}

// ---------------- Flash attention: fp16, ctx-sorted, BKV=64 tiles ----------------
// Serial softmax overhead (shuffle-max chain, rescale, barrier) paid per 64 keys
// instead of per 32 -> halves the latency-bound per-key cost. 2 buffers, ONE
// __syncthreads per tile (stage-after-sync makes the 2-buffer overwrite safe).
// Dynamic smem 55.3 KB (static cap is 48 KB). Row stride 36 words everywhere:
// bank = (4g + tq + 8c) mod 32 covers all banks -> conflict-free.
#define AKBUF (64*36)        // words per K buffer
#define AVBUF (64*36)        // words per V^T buffer
__global__ __launch_bounds__(256, 2) void attn_tc_kernel() {
    extern __shared__ uint32_t asm_[];
    uint32_t* Ksw = asm_;                    // [2][64][36]
    uint32_t* Vtw = asm_ + 2 * AKBUF;        // [2][64][36]
    uint32_t* Psw = asm_ + 4 * AKBUF;        // [8][16][36]

    int t    = threadIdx.x;
    int lane = t & 31;
    int w    = t >> 5;
    int g    = lane >> 2;
    int tq   = lane & 3;

    int b  = blockIdx.z;
    int h  = blockIdx.y;
    int qrow = blockIdx.x * 128 + w * 16;     // sorted position
    int nctx = g_nctx[b];

    bool all_ctx = (blockIdx.x * 128 + 128) <= nctx;
    int NT_cta = all_ctx ? (nctx + 63) / 64 : (SEQ / 64);

    uint32_t qa[4][4];
    {
        const __half* qb = g_qh + (size_t)(b * SEQ + qrow) * DMODEL + h * HDIM;
#pragma unroll
        for (int kst = 0; kst < 4; kst++) {
            qa[kst][0] = *(const uint32_t*)&qb[(size_t)g       * DMODEL + kst*16 + 2*tq    ];
            qa[kst][1] = *(const uint32_t*)&qb[(size_t)(g + 8) * DMODEL + kst*16 + 2*tq    ];
            qa[kst][2] = *(const uint32_t*)&qb[(size_t)g       * DMODEL + kst*16 + 2*tq + 8];
            qa[kst][3] = *(const uint32_t*)&qb[(size_t)(g + 8) * DMODEL + kst*16 + 2*tq + 8];
        }
    }
    float rf0 = (qrow + g     < nctx) ? 1.f : 0.f;
    float rf1 = (qrow + g + 8 < nctx) ? 1.f : 0.f;

    float o[8][4];
#pragma unroll
    for (int nt = 0; nt < 8; nt++)
#pragma unroll
        for (int c = 0; c < 4; c++) o[nt][c] = 0.f;
    float m0r = -1e30f, m1r = -1e30f, l0 = 0.f, l1 = 0.f;

    const __half* kb_g = g_kh + (size_t)(b * SEQ) * DMODEL + h * HDIM;
    const __half* vb_g = g_vh + ((size_t)b * NHEAD + h) * HDIM * SEQ;

    uint32_t ks_s = (uint32_t)__cvta_generic_to_shared(Ksw);
    uint32_t vs_s = (uint32_t)__cvta_generic_to_shared(Vtw);

    // staging: K 64 rows x 8 chunks + V^T 64 rows x 8 chunks; 2 chunks each per thread
    auto stage = [&](int buf, int kt) {
#pragma unroll
        for (int u = 0; u < 2; u++) {
            int c = t + 256 * u;             // 0..511
            int row = c >> 3, cc = c & 7;
            uint32_t soff = ((uint32_t)buf * AKBUF + (uint32_t)(row * 36 + cc * 4)) * 4;
            cp_async16(ks_s + soff, kb_g + (size_t)(kt + row) * DMODEL + cc * 8);
            cp_async16(vs_s + soff, vb_g + (size_t)row * SEQ + kt + cc * 8);
        }
        cp_commit();
    };

    stage(0, 0);

    for (int tile = 0; tile < NT_cta; tile++) {
        int buf = tile & 1;
        cp_wait0();
        __syncthreads();
        if (tile + 1 < NT_cta) stage(buf ^ 1, (tile + 1) * 64);

        const uint32_t* Kt = Ksw + buf * AKBUF;
        const uint32_t* Vt = Vtw + buf * AVBUF;
        uint32_t* Pw = Psw + w * (16 * 36);
        int k0b = tile * 64;

        // ---- S = Q K^T (16 x 64): 32 mmas, 8 independent chains ----
        float sacc[8][4];
#pragma unroll
        for (int nt = 0; nt < 8; nt++)
#pragma unroll
            for (int c = 0; c < 4; c++) sacc[nt][c] = 0.f;
#pragma unroll
        for (int kst = 0; kst < 4; kst++) {
#pragma unroll
            for (int nt = 0; nt < 8; nt++) {
                uint32_t bf[2];
                bf[0] = Kt[(nt*8 + g) * 36 + kst*8 + tq    ];
                bf[1] = Kt[(nt*8 + g) * 36 + kst*8 + tq + 4];
                mma_f16(sacc[nt], qa[kst], bf, sacc[nt]);
            }
        }

        // ---- mask (additive -1e30; only when tile straddles/exceeds ctx region) ----
        if (k0b + 64 > nctx) {
#pragma unroll
            for (int nt = 0; nt < 8; nt++) {
                int col = k0b + nt*8 + 2*tq;
                float k0m = (col     < nctx) ? 0.f : -1e30f;
                float k1m = (col + 1 < nctx) ? 0.f : -1e30f;
                sacc[nt][0] = fmaf(rf0, k0m, sacc[nt][0]);
                sacc[nt][1] = fmaf(rf0, k1m, sacc[nt][1]);
                sacc[nt][2] = fmaf(rf1, k0m, sacc[nt][2]);
                sacc[nt][3] = fmaf(rf1, k1m, sacc[nt][3]);
            }
        }

        // ---- online softmax (once per 64 keys) ----
        float mx0 = -1e30f, mx1 = -1e30f;
#pragma unroll
        for (int nt = 0; nt < 8; nt++) {
            mx0 = fmaxf(mx0, fmaxf(sacc[nt][0], sacc[nt][1]));
            mx1 = fmaxf(mx1, fmaxf(sacc[nt][2], sacc[nt][3]));
        }
        mx0 = fmaxf(mx0, __shfl_xor_sync(0xffffffffu, mx0, 1));
        mx0 = fmaxf(mx0, __shfl_xor_sync(0xffffffffu, mx0, 2));
        mx1 = fmaxf(mx1, __shfl_xor_sync(0xffffffffu, mx1, 1));
        mx1 = fmaxf(mx1, __shfl_xor_sync(0xffffffffu, mx1, 2));

        float mn0 = fmaxf(m0r, mx0), mn1 = fmaxf(m1r, mx1);
        float corr0 = __expf(m0r - mn0), corr1 = __expf(m1r - mn1);
        m0r = mn0; m1r = mn1;

        float rs0 = 0.f, rs1 = 0.f;
        __syncwarp();
#pragma unroll
        for (int nt = 0; nt < 8; nt++) {
            float p00 = __expf(sacc[nt][0] - mn0);
            float p01 = __expf(sacc[nt][1] - mn0);
            float p10 = __expf(sacc[nt][2] - mn1);
            float p11 = __expf(sacc[nt][3] - mn1);
            rs0 += p00 + p01; rs1 += p10 + p11;
            int pw = nt*4 + tq;
            Pw[(g    ) * 36 + pw] = pack_h2(p00, p01);
            Pw[(g + 8) * 36 + pw] = pack_h2(p10, p11);
        }
        rs0 += __shfl_xor_sync(0xffffffffu, rs0, 1);
        rs0 += __shfl_xor_sync(0xffffffffu, rs0, 2);
        rs1 += __shfl_xor_sync(0xffffffffu, rs1, 1);
        rs1 += __shfl_xor_sync(0xffffffffu, rs1, 2);
        l0 = l0 * corr0 + rs0;
        l1 = l1 * corr1 + rs1;

#pragma unroll
        for (int nt = 0; nt < 8; nt++) {
            o[nt][0] *= corr0; o[nt][1] *= corr0;
            o[nt][2] *= corr1; o[nt][3] *= corr1;
        }
        __syncwarp();

        // ---- O += P V (16 x 64, k=64): 32 mmas ----
#pragma unroll
        for (int c2 = 0; c2 < 4; c2++) {
            uint32_t ap[4];
            ap[0] = Pw[(g    ) * 36 + c2*8 + tq    ];
            ap[1] = Pw[(g + 8) * 36 + c2*8 + tq    ];
            ap[2] = Pw[(g    ) * 36 + c2*8 + tq + 4];
            ap[3] = Pw[(g + 8) * 36 + c2*8 + tq + 4];
#pragma unroll
            for (int nt = 0; nt < 8; nt++) {
                uint32_t bf[2];
                bf[0] = Vt[(nt*8 + g) * 36 + c2*8 + tq    ];
                bf[1] = Vt[(nt*8 + g) * 36 + c2*8 + tq + 4];
                mma_f16(o[nt], ap, bf, o[nt]);
            }
        }
    }

    // ---- normalize + write back to ORIGINAL rows as HALF (O GEMM input) ----
    float inv0 = 1.f / l0, inv1 = 1.f / l1;
    int orow0 = g_perm[b * SEQ + qrow + g    ];
    int orow1 = g_perm[b * SEQ + qrow + g + 8];
    __half* ob0 = g_atth + ((size_t)b * SEQ + orow0) * DMODEL + h * HDIM;
    __half* ob1 = g_atth + ((size_t)b * SEQ + orow1) * DMODEL + h * HDIM;
#pragma unroll
    for (int nt = 0; nt < 8; nt++) {
        int col = nt*8 + 2*tq;
        *(uint32_t*)&ob0[col] = pack_h2(o[nt][0] * inv0, o[nt][1] * inv0);
        *(uint32_t*)&ob1[col] = pack_h2(o[nt][2] * inv1, o[nt][3] * inv1);
    }
}

// ---------------- launch ----------------
extern "C" void kernel_launch(void* const* d_in, const int* in_sizes, int n_in,
                              void* d_out, int out_size) {
    const float* x   = (const float*)d_in[0];
    const void*  ctx = d_in[1];
    const float* Wq  = (const float*)d_in[2];
    const float* bq  = (const float*)d_in[3];
    const float* Wk  = (const float*)d_in[4];
    const float* bk  = (const float*)d_in[5];
    const float* Wv  = (const float*)d_in[6];
    const float* bv  = (const float*)d_in[7];
    const float* Wo  = (const float*)d_in[8];
    const float* bo  = (const float*)d_in[9];
    float* out = (float*)d_out;

    __half *qh, *kh, *vh, *ath, *xh, *wqh, *wkh, *wvh, *woh;
    cudaGetSymbolAddress((void**)&qh,  g_qh);
    cudaGetSymbolAddress((void**)&kh,  g_kh);
    cudaGetSymbolAddress((void**)&vh,  g_vh);
    cudaGetSymbolAddress((void**)&ath, g_atth);
    cudaGetSymbolAddress((void**)&xh,  g_xh);
    cudaGetSymbolAddress((void**)&wqh, g_wqh);
    cudaGetSymbolAddress((void**)&wkh, g_wkh);
    cudaGetSymbolAddress((void**)&wvh, g_wvh);
    cudaGetSymbolAddress((void**)&woh, g_woh);

    int asmem = (4 * AKBUF + 8 * 16 * 36) * (int)sizeof(uint32_t);  // 55296 B
    static bool attr_set = false;
    if (!attr_set) {
        cudaFuncSetAttribute(gemm_f16_kernel, cudaFuncAttributeMaxDynamicSharedMemorySize,
                             4 * GBUFH * (int)sizeof(__half));
        cudaFuncSetAttribute(attn_tc_kernel, cudaFuncAttributeMaxDynamicSharedMemorySize, asmem);
        attr_set = true;
    }

    detect_dtype_kernel<<<1, 1024>>>((const unsigned char*)ctx, MTOT);
    build_perm_kernel<<<BATCH, 256>>>(ctx);

    half_convert_all_kernel<<<1184, 256>>>(x, Wq, Wk, Wv, Wo);

    int smem = 4 * GBUFH * (int)sizeof(__half);   // 73728 B

    dim3 gqkv(DMODEL / 128, MTOT / 128, 3);
    gemm_f16_kernel<<<gqkv, 256, smem>>>(xh, wqh, bq, qh, wkh, bk, kh, wvh, bv, vh, 1);

    attn_tc_kernel<<<dim3(SEQ / 128, NHEAD, BATCH), 256, asmem>>>();

    dim3 go(DMODEL / 128, MTOT / 128, 1);
    gemm_f16_kernel<<<go, 256, smem>>>(ath, woh, bo, out, woh, bo, out, woh, bo, out, 0);
}